// round 7
// baseline (speedup 1.0000x reference)
#include <cuda_runtime.h>

// out[b] = 0.5 * mean(sigmoid(conv2d_valid(data, w4x4) + b)) for all b (broadcast).
// Quantum term is exactly 0: theta in {0, pi}; RX(pi) = -i*X and the CX chain are
// basis permutations / global phases on the uniform H^n|0> state => qexp[b] = 0.

#define IMG 64
#define OUT 61
#define NPOS (OUT * OUT)          // 3721
#define NBATCH 256
#define STRIPS 8                  // 8-output-row strips per image
#define NB (NBATCH * STRIPS)      // 2048 CTAs
#define THREADS 128
#define CHUNK 4                   // x-positions per thread (16 chunks per row)
#define NBUCKET 64
#define BSTRIDE 32                // floats -> 128B apart (distinct L2 slices)

__device__ float        g_part[NBUCKET * BSTRIDE];   // zero-initialized
__device__ unsigned int g_count = 0u;

__global__ __launch_bounds__(THREADS)
void conv_sigmoid_mean_kernel(const float* __restrict__ data,
                              const float* __restrict__ w,
                              const float* __restrict__ b,
                              float* __restrict__ out) {
    // max 11 input rows; +4 floats pad: chunk 15 reads one float4 past a row end
    __shared__ float img_s[11 * IMG + 4];
    __shared__ float sw[16];
    __shared__ float warp_sums[THREADS / 32];
    __shared__ float red[NBUCKET];
    __shared__ int   is_last;
    __shared__ float tot;

    const int bid = blockIdx.x;
    const int tid = threadIdx.x;
    const int img = bid >> 3;          // image index
    const int oct = bid & 7;           // strip index
    const int y0  = oct * STRIPS;      // first output row: 0,8,...,56
    const int nrowsO = (oct == 7) ? (OUT - 56) : STRIPS;   // 5 or 8
    const int nrows  = nrowsO + 3;                         // input rows: 8 or 11

    // Load input strip: nrows*16 float4 (<=176), 1-2 per thread
    const float4* src4 = reinterpret_cast<const float4*>(
        data + (size_t)img * IMG * IMG + (size_t)y0 * IMG);
    float4* img4 = reinterpret_cast<float4*>(img_s);
    const int nf4 = nrows * (IMG / 4);
    for (int i = tid; i < nf4; i += THREADS) {
        img4[i] = src4[i];
    }
    if (tid < 16) sw[tid] = w[tid];
    __syncthreads();

    float lsum = 0.0f;

    const int ly    = tid >> 4;        // local output row 0..7
    const int chunk = tid & 15;        // 0..15
    const int x0    = chunk * CHUNK;   // 0,4,...,60 (float4-aligned)

    if (ly < nrowsO) {
        const float bias = b[0];
        float acc[CHUNK];
        #pragma unroll
        for (int p = 0; p < CHUNK; p++) acc[p] = bias;

        #pragma unroll
        for (int i = 0; i < 4; i++) {
            // 7-value window for this input row: 2 x LDS.128
            const float4* r = img4 + (ly + i) * (IMG / 4) + (x0 >> 2);
            float4 v0 = r[0], v1 = r[1];
            float win[7] = {v0.x, v0.y, v0.z, v0.w, v1.x, v1.y, v1.z};
            #pragma unroll
            for (int j = 0; j < 4; j++) {
                const float wij = sw[i * 4 + j];
                #pragma unroll
                for (int p = 0; p < CHUNK; p++) {
                    acc[p] = fmaf(win[p + j], wij, acc[p]);
                }
            }
        }

        #pragma unroll
        for (int p = 0; p < CHUNK; p++) {
            if (x0 + p < OUT) {                      // mask tail of chunk 15
                lsum += 1.0f / (1.0f + __expf(-acc[p]));
            }
        }
    }

    // warp reduce
    #pragma unroll
    for (int off = 16; off > 0; off >>= 1)
        lsum += __shfl_xor_sync(0xFFFFFFFFu, lsum, off);

    const int wid = tid >> 5;
    const int lid = tid & 31;
    if (lid == 0) warp_sums[wid] = lsum;
    __syncthreads();

    if (tid == 0) {
        float s = warp_sums[0] + warp_sums[1] + warp_sums[2] + warp_sums[3];
        atomicAdd(&g_part[(bid & (NBUCKET - 1)) * BSTRIDE], s);
        __threadfence();
        unsigned int prev = atomicAdd(&g_count, 1u);
        is_last = (prev == (unsigned)(NB - 1)) ? 1 : 0;
    }
    __syncthreads();

    if (is_last) {
        // all prior g_part adds are visible (each CTA fenced before counting)
        if (tid < NBUCKET) red[tid] = g_part[tid * BSTRIDE];
        __syncthreads();
        if (tid == 0) {
            float s = 0.0f;
            #pragma unroll
            for (int i = 0; i < NBUCKET; i++) s += red[i];
            tot = s * (0.5f / (float)(NBATCH * NPOS));
        }
        __syncthreads();
        const float val = tot;
        out[tid]           = val;      // 128 threads cover 256 outputs
        out[tid + THREADS] = val;
        // self-clean for the next graph replay
        if (tid < NBUCKET) g_part[tid * BSTRIDE] = 0.0f;
        if (tid == 0)      g_count = 0u;
        __threadfence();
    }
}

extern "C" void kernel_launch(void* const* d_in, const int* in_sizes, int n_in,
                              void* d_out, int out_size) {
    const float* data = (const float*)d_in[0];   // 256*1*64*64
    const float* w    = (const float*)d_in[1];   // 1*1*4*4
    const float* b    = (const float*)d_in[2];   // 1
    float* out = (float*)d_out;                  // 256 floats

    conv_sigmoid_mean_kernel<<<NB, THREADS>>>(data, w, b, out);
}

// round 8
// speedup vs baseline: 1.0269x; 1.0269x over previous
#include <cuda_runtime.h>

// out[b] = 0.5 * mean(sigmoid(conv2d_valid(data, w4x4) + b)) for all b (broadcast).
// Quantum term is exactly 0 (RX(pi) = -i*X and CX chain are basis perms / global
// phases on the uniform H^n|0> state => qexp[b] = 0 for all b).
// sigmoid(x) = 0.5 + 0.5*tanh(x/2): fold 0.5 into weights/bias, accumulate tanh,
// final = 0.25 + 0.25*mean(tanh).

#define IMG 64
#define OUT 61
#define NPOS (OUT * OUT)          // 3721
#define NBATCH 256
#define THREADS 512
#define NBUCKET 16
#define BSTRIDE 32                // floats -> 128B apart

__device__ float        g_part[NBUCKET * BSTRIDE];   // zero-initialized
__device__ unsigned int g_count = 0u;

__device__ __forceinline__ float tanh_fast(float x) {
    float r;
    asm("tanh.approx.f32 %0, %1;" : "=f"(r) : "f"(x));
    return r;
}

__global__ __launch_bounds__(THREADS, 2)
void conv_sigmoid_mean_kernel(const float* __restrict__ data,
                              const float* __restrict__ w,
                              const float* __restrict__ b,
                              float* __restrict__ out) {
    __shared__ float warp_sums[THREADS / 32];
    __shared__ int   is_last;
    __shared__ float tot;

    const int n   = blockIdx.x;
    const int tid = threadIdx.x;
    const int y     = tid >> 3;        // 0..63 (rows 61..63 idle)
    const int chunk = tid & 7;         // 0..7
    const int x0    = chunk * 8;       // 0,8,...,56

    // Pre-scaled weights/bias (uniform-address loads -> L1 broadcast)
    float sw[16];
    #pragma unroll
    for (int i = 0; i < 16; i++) sw[i] = 0.5f * __ldg(w + i);
    const float bias05 = 0.5f * __ldg(b);

    float lsum = 0.0f;

    if (y < OUT) {
        const float4* img4 = reinterpret_cast<const float4*>(data + (size_t)n * IMG * IMG);

        float acc[8];
        #pragma unroll
        for (int p = 0; p < 8; p++) acc[p] = bias05;

        #pragma unroll
        for (int i = 0; i < 4; i++) {
            const float4* r = img4 + (y + i) * (IMG / 4) + (x0 >> 2);
            float4 v0 = __ldg(r);
            float4 v1 = __ldg(r + 1);
            // third float4 only feeds outputs x>=61 (masked); chunk 7's r+2 can
            // run past the buffer on the last image -> zero-fill instead.
            float4 v2 = (chunk < 7) ? __ldg(r + 2) : make_float4(0.f, 0.f, 0.f, 0.f);
            float win[12] = {v0.x, v0.y, v0.z, v0.w,
                             v1.x, v1.y, v1.z, v1.w,
                             v2.x, v2.y, v2.z, v2.w};
            #pragma unroll
            for (int j = 0; j < 4; j++) {
                const float wij = sw[i * 4 + j];
                #pragma unroll
                for (int p = 0; p < 8; p++) {
                    acc[p] = fmaf(win[p + j], wij, acc[p]);
                }
            }
        }

        #pragma unroll
        for (int p = 0; p < 8; p++) {
            if (x0 + p < OUT) {
                lsum += tanh_fast(acc[p]);     // sigmoid sans affine (folded out)
            }
        }
    }

    // warp reduce
    #pragma unroll
    for (int off = 16; off > 0; off >>= 1)
        lsum += __shfl_xor_sync(0xFFFFFFFFu, lsum, off);

    const int wid = tid >> 5;
    const int lid = tid & 31;
    if (lid == 0) warp_sums[wid] = lsum;
    __syncthreads();

    if (tid == 0) {
        float s = 0.0f;
        #pragma unroll
        for (int i = 0; i < THREADS / 32; i++) s += warp_sums[i];
        atomicAdd(&g_part[(n & (NBUCKET - 1)) * BSTRIDE], s);
        __threadfence();
        unsigned int prev = atomicAdd(&g_count, 1u);
        is_last = (prev == (unsigned)(NBATCH - 1)) ? 1 : 0;
        if (is_last) {
            // all prior g_part adds visible (each CTA fenced before counting)
            float t = 0.0f;
            #pragma unroll
            for (int i = 0; i < NBUCKET; i++) t += g_part[i * BSTRIDE];
            tot = 0.25f + 0.25f * t / (float)(NBATCH * NPOS);
        }
    }
    __syncthreads();

    if (is_last) {
        if (tid < NBATCH) out[tid] = tot;
        // self-clean for the next graph replay
        if (tid < NBUCKET) g_part[tid * BSTRIDE] = 0.0f;
        if (tid == 0)      g_count = 0u;
        __threadfence();
    }
}

extern "C" void kernel_launch(void* const* d_in, const int* in_sizes, int n_in,
                              void* d_out, int out_size) {
    const float* data = (const float*)d_in[0];   // 256*1*64*64
    const float* w    = (const float*)d_in[1];   // 1*1*4*4
    const float* b    = (const float*)d_in[2];   // 1
    float* out = (float*)d_out;                  // 256 floats

    conv_sigmoid_mean_kernel<<<NBATCH, THREADS>>>(data, w, b, out);
}

// round 10
// speedup vs baseline: 1.2647x; 1.2316x over previous
#include <cuda_runtime.h>

// out[b] = 0.5 * mean(sigmoid(conv2d_valid(data, w4x4) + b)) for all b (broadcast).
// Quantum term is exactly 0 (RX(pi) = -i*X and the CX chain are basis perms /
// global phases on the uniform H^n|0> state => qexp[b] = 0 for all b).
// sigmoid(x) = 0.5 + 0.5*tanh(x/2): fold 0.5 into weights/bias, accumulate tanh,
// final = 0.25 + 0.25*mean(tanh).

#define IMG 64
#define OUT 61
#define NPOS (OUT * OUT)          // 3721
#define NBATCH 256
#define NCTA 128                  // one balanced wave, 2 images per CTA
#define THREADS 256
#define NBUCKET 16
#define BSTRIDE 32                // floats -> 128B apart

__device__ float        g_part[NBUCKET * BSTRIDE];   // zero-initialized
__device__ unsigned int g_count = 0u;

__device__ __forceinline__ float tanh_fast(float x) {
    float r;
    asm("tanh.approx.f32 %0, %1;" : "=f"(r) : "f"(x));
    return r;
}

__global__ __launch_bounds__(THREADS)
void conv_sigmoid_mean_kernel(const float* __restrict__ data,
                              const float* __restrict__ w,
                              const float* __restrict__ b,
                              float* __restrict__ out) {
    __shared__ float warp_sums[THREADS / 32];
    __shared__ int   is_last;
    __shared__ float tot;

    const int t     = threadIdx.x;
    const int local = t & 127;
    const int img   = 2 * blockIdx.x + (t >> 7);
    const int blk   = local >> 3;      // 0..15 row-blocks
    const int chunk = local & 7;       // 0..7 x-chunks
    const int x0    = chunk * 8;
    const int y0    = blk * 4;         // blk 15 -> only row 60 valid

    // Pre-scaled weights/bias
    float sw[16];
    #pragma unroll
    for (int i = 0; i < 16; i++) sw[i] = 0.5f * __ldg(w + i);
    const float bias05 = 0.5f * __ldg(b);

    // Front-batch the entire 7-row x 12-col input tile: 21 independent LDG.128
    const float4* img4 = reinterpret_cast<const float4*>(data)
                       + (size_t)img * (IMG * IMG / 4) + (x0 >> 2);
    float4 R[7][3];
    #pragma unroll
    for (int s = 0; s < 7; s++) {
        int ry = y0 + s;
        ry = (ry > 63) ? 63 : ry;              // clamp (garbage rows masked later)
        const float4* r = img4 + ry * (IMG / 4);
        R[s][0] = __ldg(r);
        R[s][1] = __ldg(r + 1);
        // chunk 7's third float4 only feeds masked outputs x>=61 (and would be OOB)
        R[s][2] = (chunk < 7) ? __ldg(r + 2) : make_float4(0.f, 0.f, 0.f, 0.f);
    }

    float lsum = 0.0f;

    #pragma unroll
    for (int k = 0; k < 4; k++) {
        if (y0 + k < OUT) {
            float acc[8];
            #pragma unroll
            for (int p = 0; p < 8; p++) acc[p] = bias05;

            #pragma unroll
            for (int i = 0; i < 4; i++) {
                const float4 v0 = R[k + i][0], v1 = R[k + i][1], v2 = R[k + i][2];
                const float win[12] = {v0.x, v0.y, v0.z, v0.w,
                                       v1.x, v1.y, v1.z, v1.w,
                                       v2.x, v2.y, v2.z, v2.w};
                #pragma unroll
                for (int j = 0; j < 4; j++) {
                    const float wij = sw[i * 4 + j];
                    #pragma unroll
                    for (int p = 0; p < 8; p++) {
                        acc[p] = fmaf(win[p + j], wij, acc[p]);
                    }
                }
            }

            #pragma unroll
            for (int p = 0; p < 8; p++) {
                if (x0 + p < OUT) {
                    lsum += tanh_fast(acc[p]);
                }
            }
        }
    }

    // warp reduce
    #pragma unroll
    for (int off = 16; off > 0; off >>= 1)
        lsum += __shfl_xor_sync(0xFFFFFFFFu, lsum, off);

    const int wid = t >> 5;
    const int lid = t & 31;
    if (lid == 0) warp_sums[wid] = lsum;
    __syncthreads();

    if (t == 0) {
        float s = 0.0f;
        #pragma unroll
        for (int i = 0; i < THREADS / 32; i++) s += warp_sums[i];
        atomicAdd(&g_part[(blockIdx.x & (NBUCKET - 1)) * BSTRIDE], s);
        __threadfence();
        unsigned int prev = atomicAdd(&g_count, 1u);
        is_last = (prev == (unsigned)(NCTA - 1)) ? 1 : 0;
        if (is_last) {
            // all prior g_part adds visible (each CTA fenced before counting)
            float tsum = 0.0f;
            #pragma unroll
            for (int i = 0; i < NBUCKET; i++) tsum += g_part[i * BSTRIDE];
            tot = 0.25f + 0.25f * tsum / (float)(NBATCH * NPOS);
        }
    }
    __syncthreads();

    if (is_last) {
        out[t] = tot;                       // THREADS == NBATCH == out_size
        // self-clean for the next graph replay
        if (t < NBUCKET) g_part[t * BSTRIDE] = 0.0f;
        if (t == 0)      g_count = 0u;
        __threadfence();
    }
}

extern "C" void kernel_launch(void* const* d_in, const int* in_sizes, int n_in,
                              void* d_out, int out_size) {
    const float* data = (const float*)d_in[0];   // 256*1*64*64
    const float* w    = (const float*)d_in[1];   // 1*1*4*4
    const float* b    = (const float*)d_in[2];   // 1
    float* out = (float*)d_out;                  // 256 floats

    conv_sigmoid_mean_kernel<<<NCTA, THREADS>>>(data, w, b, out);
}

// round 11
// speedup vs baseline: 1.2694x; 1.0037x over previous
#include <cuda_runtime.h>

// out[b] = 0.5 * mean(sigmoid(conv2d_valid(data, w4x4) + b)) for all b (broadcast).
// Quantum term is exactly 0 (RX(pi) = -i*X and the CX chain are basis perms /
// global phases on the uniform H^n|0> state => qexp[b] = 0 for all b).
// sigmoid(x) = 0.5 + 0.5*tanh(x/2): fold 0.5 into weights/bias, accumulate tanh,
// final = 0.25 + 0.25*mean(tanh).

#define IMG 64
#define OUT 61
#define NPOS (OUT * OUT)          // 3721
#define NBATCH 256
#define NCTA 128                  // one balanced wave, 2 images per CTA
#define THREADS 512
#define NBUCKET 16
#define BSTRIDE 32                // floats -> 128B apart

__device__ float        g_part[NBUCKET * BSTRIDE];   // zero-initialized
__device__ unsigned int g_count = 0u;

__device__ __forceinline__ float tanh_fast(float x) {
    float r;
    asm("tanh.approx.f32 %0, %1;" : "=f"(r) : "f"(x));
    return r;
}

__global__ __launch_bounds__(THREADS)
void conv_sigmoid_mean_kernel(const float* __restrict__ data,
                              const float* __restrict__ w,
                              const float* __restrict__ b,
                              float* __restrict__ out) {
    __shared__ float warp_sums[THREADS / 32];
    __shared__ int   is_last;
    __shared__ float tot;

    const int t     = threadIdx.x;
    const int local = t & 255;                      // 256 threads per image
    const int img   = (blockIdx.x << 1) | (t >> 8); // 2 images per CTA
    const int blk   = local >> 4;                   // 0..15 row-blocks (4 rows each)
    const int chunk = local & 15;                   // 0..15 x-chunks (4 cols each)
    const int x0    = chunk * 4;                    // 0,4,...,60
    const int y0    = blk * 4;                      // blk 15 -> only row 60 valid

    // Pre-scaled weights/bias (uniform loads, kept in registers)
    float sw[16];
    #pragma unroll
    for (int i = 0; i < 16; i++) sw[i] = 0.5f * __ldg(w + i);
    const float bias05 = 0.5f * __ldg(b);

    // Front-batch the entire 7-row x 8-col input tile: 14 independent LDG.128
    const float4* img4 = reinterpret_cast<const float4*>(data)
                       + (size_t)img * (IMG * IMG / 4) + (x0 >> 2);
    float4 R0[7], R1[7];
    #pragma unroll
    for (int s = 0; s < 7; s++) {
        int ry = y0 + s;
        ry = (ry > 63) ? 63 : ry;                   // clamp; garbage rows masked later
        const float4* r = img4 + ry * (IMG / 4);
        R0[s] = __ldg(r);
        // chunk 15's second float4 only feeds masked outputs x>=61 (and would be OOB)
        R1[s] = (chunk < 15) ? __ldg(r + 1) : make_float4(0.f, 0.f, 0.f, 0.f);
    }

    float lsum = 0.0f;

    #pragma unroll
    for (int k = 0; k < 4; k++) {
        if (y0 + k < OUT) {
            float acc[4];
            #pragma unroll
            for (int p = 0; p < 4; p++) acc[p] = bias05;

            #pragma unroll
            for (int i = 0; i < 4; i++) {
                const float4 v0 = R0[k + i], v1 = R1[k + i];
                const float win[8] = {v0.x, v0.y, v0.z, v0.w,
                                      v1.x, v1.y, v1.z, v1.w};
                #pragma unroll
                for (int j = 0; j < 4; j++) {
                    const float wij = sw[i * 4 + j];
                    #pragma unroll
                    for (int p = 0; p < 4; p++) {
                        acc[p] = fmaf(win[p + j], wij, acc[p]);
                    }
                }
            }

            #pragma unroll
            for (int p = 0; p < 4; p++) {
                if (x0 + p < OUT) {
                    lsum += tanh_fast(acc[p]);
                }
            }
        }
    }

    // warp reduce
    #pragma unroll
    for (int off = 16; off > 0; off >>= 1)
        lsum += __shfl_xor_sync(0xFFFFFFFFu, lsum, off);

    const int wid = t >> 5;
    const int lid = t & 31;
    if (lid == 0) warp_sums[wid] = lsum;
    __syncthreads();

    if (t == 0) {
        float s = 0.0f;
        #pragma unroll
        for (int i = 0; i < THREADS / 32; i++) s += warp_sums[i];
        atomicAdd(&g_part[(blockIdx.x & (NBUCKET - 1)) * BSTRIDE], s);
        __threadfence();
        unsigned int prev = atomicAdd(&g_count, 1u);
        is_last = (prev == (unsigned)(NCTA - 1)) ? 1 : 0;
        if (is_last) {
            // all prior g_part adds visible (each CTA fenced before counting)
            float tsum = 0.0f;
            #pragma unroll
            for (int i = 0; i < NBUCKET; i++) tsum += g_part[i * BSTRIDE];
            tot = 0.25f + 0.25f * tsum / (float)(NBATCH * NPOS);
        }
    }
    __syncthreads();

    if (is_last) {
        if (t < NBATCH) out[t] = tot;
        // self-clean for the next graph replay
        if (t < NBUCKET) g_part[t * BSTRIDE] = 0.0f;
        if (t == 0)      g_count = 0u;
        __threadfence();
    }
}

extern "C" void kernel_launch(void* const* d_in, const int* in_sizes, int n_in,
                              void* d_out, int out_size) {
    const float* data = (const float*)d_in[0];   // 256*1*64*64
    const float* w    = (const float*)d_in[1];   // 1*1*4*4
    const float* b    = (const float*)d_in[2];   // 1
    float* out = (float*)d_out;                  // 256 floats

    conv_sigmoid_mean_kernel<<<NCTA, THREADS>>>(data, w, b, out);
}